// round 10
// baseline (speedup 1.0000x reference)
#include <cuda_runtime.h>
#include <cuda_bf16.h>
#include <cstdint>

// ============================================================================
// Problem constants
// ============================================================================
#define B_ROWS 8192

#define MT 128
#define NT 256
#define KC 64
#define GEMM_THREADS 512            // 16 warps: M-split 2 x N-split 8

#define STG_A_HI 0
#define STG_A_LO 16384
#define STG_W_HI 32768
#define STG_W_LO 65536
#define STAGE_BYTES 98304           // 96 KB
#define SMEM_TOTAL (2 * STAGE_BYTES)

// ============================================================================
// Scratch (__device__ globals; no cudaMalloc allowed)
// w1/w5 oversized by 64 rows: tail CTAs with NPT=1 cover 128 cols and read
// garbage rows >= Nreal; their results are discarded by the epilogue guard.
// ============================================================================
__device__ __nv_bfloat16 g_xHi[B_ROWS * 192];
__device__ __nv_bfloat16 g_xLo[B_ROWS * 192];

__device__ __nv_bfloat16 g_w1Hi[2176 * 192],           g_w1Lo[2176 * 192];
__device__ __nv_bfloat16 g_w2Hi[(size_t)4224 * 2112],  g_w2Lo[(size_t)4224 * 2112];
__device__ __nv_bfloat16 g_w3Hi[(size_t)8448 * 4224],  g_w3Lo[(size_t)8448 * 4224];
__device__ __nv_bfloat16 g_w4Hi[(size_t)4224 * 8448],  g_w4Lo[(size_t)4224 * 8448];
__device__ __nv_bfloat16 g_w5Hi[128 * 4224],           g_w5Lo[128 * 4224];

__device__ __nv_bfloat16 g_actAHi[(size_t)B_ROWS * 8448], g_actALo[(size_t)B_ROWS * 8448];
__device__ __nv_bfloat16 g_actBHi[(size_t)B_ROWS * 4224], g_actBLo[(size_t)B_ROWS * 4224];

// L5 split-K partials: 2 x [8192, 64] fp32
__device__ __align__(16) float g_qpart[2 * B_ROWS * 64];

// ============================================================================
// PTX helpers
// ============================================================================
__device__ __forceinline__ uint32_t smem_u32(const void* p) {
    uint32_t a;
    asm("{ .reg .u64 t; cvta.to.shared.u64 t, %1; cvt.u32.u64 %0, t; }"
        : "=r"(a) : "l"(p));
    return a;
}

#define CP_ASYNC16(dst, src) \
    asm volatile("cp.async.cg.shared.global [%0], [%1], 16;" :: "r"(dst), "l"(src))

#define CP_COMMIT() asm volatile("cp.async.commit_group;" ::: "memory")
#define CP_WAIT(n)  asm volatile("cp.async.wait_group %0;" :: "n"(n) : "memory")

#define LDSM4(r, addr) \
    asm volatile("ldmatrix.sync.aligned.m8n8.x4.shared.b16 {%0,%1,%2,%3}, [%4];" \
                 : "=r"((r)[0]), "=r"((r)[1]), "=r"((r)[2]), "=r"((r)[3]) : "r"(addr))

#define MMA_BF16(d, a, b0, b1) \
    asm volatile("mma.sync.aligned.m16n8k16.row.col.f32.bf16.bf16.f32 " \
                 "{%0,%1,%2,%3},{%4,%5,%6,%7},{%8,%9},{%0,%1,%2,%3};" \
                 : "+f"((d)[0]), "+f"((d)[1]), "+f"((d)[2]), "+f"((d)[3]) \
                 : "r"((a)[0]), "r"((a)[1]), "r"((a)[2]), "r"((a)[3]), \
                   "r"(b0), "r"(b1))

__device__ __forceinline__ uint32_t swz(int r, int c) {
    return (uint32_t)(r * 128 + ((c ^ (r & 7)) << 4));
}

// ============================================================================
// GEMM body: 2-stage KC=64 double buffer, 512 threads (16 warps).
// Warp tile: 64 x (NPT*16); 8 n-warp groups cover NPT*128 columns.
// NPT=2 -> 256-col tile, NPT=1 -> 128-col tile.
// Split-K: part p of grid.y handles kLen K-columns at offset p*kLen.
// OUTFMT 0: bf16 hi/lo pair, 2: fp32 (bias nullable).
// ============================================================================
template<int NPT, int OUTFMT>
__device__ __forceinline__ void gemm_body(
    char* smem,
    const __nv_bfloat16* __restrict__ aHi, const __nv_bfloat16* __restrict__ aLo,
    const __nv_bfloat16* __restrict__ wHi, const __nv_bfloat16* __restrict__ wLo,
    const float* __restrict__ bias,
    __nv_bfloat16* __restrict__ oHi, __nv_bfloat16* __restrict__ oLo,
    float* __restrict__ oF,
    int Nreal, int Kstride, int doRelu, int mBlocks, int kLen, size_t partStride)
{
    const uint32_t sb = smem_u32(smem);
    const int tid  = threadIdx.x;
    const int wid  = tid >> 5;          // 0..15
    const int lane = tid & 31;
    const int by   = blockIdx.y;
    const int part = by / mBlocks;
    const int m0 = (by - part * mBlocks) * MT;
    const int n0 = blockIdx.x * NT;
    const int kOff = part * kLen;
    aHi += kOff; aLo += kOff; wHi += kOff; wLo += kOff;
    if (OUTFMT == 2) oF += (size_t)part * partStride;
    const int nChunks = kLen / KC;

    auto load_chunk = [&](int c, int stage) {
        const uint32_t base = sb + stage * STAGE_BYTES;
        const int k0 = c * KC;
        #pragma unroll
        for (int i = 0; i < 2; i++) {                    // A: 1024 x 16B
            int j = tid + i * GEMM_THREADS;
            int r = j >> 3, cc = j & 7;
            uint32_t d = base + swz(r, cc);
            size_t so = (size_t)(m0 + r) * Kstride + k0 + cc * 8;
            CP_ASYNC16(d + STG_A_HI, aHi + so);
            CP_ASYNC16(d + STG_A_LO, aLo + so);
        }
        #pragma unroll
        for (int i = 0; i < 2 * NPT; i++) {              // W: NPT*128 rows x 8 x 16B
            int j = tid + i * GEMM_THREADS;
            int r = j >> 3, cc = j & 7;
            uint32_t d = base + swz(r, cc);
            size_t so = (size_t)(n0 + r) * Kstride + k0 + cc * 8;
            CP_ASYNC16(d + STG_W_HI, wHi + so);
            CP_ASYNC16(d + STG_W_LO, wLo + so);
        }
    };

    float acc[4][2 * NPT][4];
    #pragma unroll
    for (int t = 0; t < 4; t++)
        #pragma unroll
        for (int nf = 0; nf < 2 * NPT; nf++)
            #pragma unroll
            for (int e = 0; e < 4; e++) acc[t][nf][e] = 0.0f;

    const int mBase = (wid & 1) * 64;
    const int nBase = (wid >> 1) * (NPT * 16);

    load_chunk(0, 0);
    CP_COMMIT();

    for (int c = 0; c < nChunks; c++) {
        if (c + 1 < nChunks) {
            load_chunk(c + 1, (c + 1) & 1);
            CP_COMMIT();
            CP_WAIT(1);
        } else {
            CP_WAIT(0);
        }
        __syncthreads();

        const uint32_t base = sb + (c & 1) * STAGE_BYTES;
        #pragma unroll
        for (int s = 0; s < 4; s++) {
            // ---- phase 1: aH terms (aH x bH, aH x bL); bH kept live ----
            uint32_t aH[4][4];
            #pragma unroll
            for (int t = 0; t < 4; t++) {
                int row = mBase + t * 16 + (lane & 15);
                int c16 = s * 2 + (lane >> 4);
                LDSM4(aH[t], base + STG_A_HI + swz(row, c16));
            }
            uint32_t bH[NPT][4];
            #pragma unroll
            for (int p = 0; p < NPT; p++) {
                int g = lane >> 3;
                int row = nBase + p * 16 + (lane & 7) + ((g >> 1) << 3);
                int c16 = s * 2 + (g & 1);
                uint32_t bL[4];
                LDSM4(bH[p], base + STG_W_HI + swz(row, c16));
                LDSM4(bL,    base + STG_W_LO + swz(row, c16));
                #pragma unroll
                for (int t = 0; t < 4; t++) {
                    MMA_BF16(acc[t][2 * p],     aH[t], bH[p][0], bH[p][1]);
                    MMA_BF16(acc[t][2 * p + 1], aH[t], bH[p][2], bH[p][3]);
                }
                #pragma unroll
                for (int t = 0; t < 4; t++) {
                    MMA_BF16(acc[t][2 * p],     aH[t], bL[0], bL[1]);
                    MMA_BF16(acc[t][2 * p + 1], aH[t], bL[2], bL[3]);
                }
            }
            // ---- phase 2: aL x bH (aH registers now dead) ----
            uint32_t aL[4][4];
            #pragma unroll
            for (int t = 0; t < 4; t++) {
                int row = mBase + t * 16 + (lane & 15);
                int c16 = s * 2 + (lane >> 4);
                LDSM4(aL[t], base + STG_A_LO + swz(row, c16));
            }
            #pragma unroll
            for (int p = 0; p < NPT; p++) {
                #pragma unroll
                for (int t = 0; t < 4; t++) {
                    MMA_BF16(acc[t][2 * p],     aL[t], bH[p][0], bH[p][1]);
                    MMA_BF16(acc[t][2 * p + 1], aL[t], bH[p][2], bH[p][3]);
                }
            }
        }
        __syncthreads();
    }

    // ---------------- epilogue ---------------------------------------------
    const int mW = m0 + mBase;
    const int nW = n0 + nBase;
    #pragma unroll
    for (int t = 0; t < 4; t++) {
        #pragma unroll
        for (int nf = 0; nf < 2 * NPT; nf++) {
            int cc = nW + nf * 8 + ((lane & 3) << 1);
            if (cc >= Nreal) continue;
            int r0 = mW + t * 16 + (lane >> 2);
            int r1 = r0 + 8;
            float bv0 = bias ? bias[cc] : 0.0f;
            float bv1 = bias ? bias[cc + 1] : 0.0f;
            float v00 = acc[t][nf][0] + bv0;
            float v01 = acc[t][nf][1] + bv1;
            float v10 = acc[t][nf][2] + bv0;
            float v11 = acc[t][nf][3] + bv1;
            if (doRelu) {
                v00 = fmaxf(v00, 0.f); v01 = fmaxf(v01, 0.f);
                v10 = fmaxf(v10, 0.f); v11 = fmaxf(v11, 0.f);
            }
            if constexpr (OUTFMT == 2) {
                *reinterpret_cast<float2*>(oF + (size_t)r0 * Nreal + cc) = make_float2(v00, v01);
                *reinterpret_cast<float2*>(oF + (size_t)r1 * Nreal + cc) = make_float2(v10, v11);
            } else {
                __nv_bfloat16 h00 = __float2bfloat16(v00), h01 = __float2bfloat16(v01);
                __nv_bfloat16 h10 = __float2bfloat16(v10), h11 = __float2bfloat16(v11);
                __nv_bfloat16 l00 = __float2bfloat16(v00 - __bfloat162float(h00));
                __nv_bfloat16 l01 = __float2bfloat16(v01 - __bfloat162float(h01));
                __nv_bfloat16 l10 = __float2bfloat16(v10 - __bfloat162float(h10));
                __nv_bfloat16 l11 = __float2bfloat16(v11 - __bfloat162float(h11));
                *reinterpret_cast<__nv_bfloat162*>(oHi + (size_t)r0 * Nreal + cc) = __nv_bfloat162(h00, h01);
                *reinterpret_cast<__nv_bfloat162*>(oHi + (size_t)r1 * Nreal + cc) = __nv_bfloat162(h10, h11);
                *reinterpret_cast<__nv_bfloat162*>(oLo + (size_t)r0 * Nreal + cc) = __nv_bfloat162(l00, l01);
                *reinterpret_cast<__nv_bfloat162*>(oLo + (size_t)r1 * Nreal + cc) = __nv_bfloat162(l10, l11);
            }
        }
    }
}

template<int OUTFMT>
__global__ void __launch_bounds__(GEMM_THREADS, 1)
gemm_bf16x3(const __nv_bfloat16* __restrict__ aHi, const __nv_bfloat16* __restrict__ aLo,
            const __nv_bfloat16* __restrict__ wHi, const __nv_bfloat16* __restrict__ wLo,
            const float* __restrict__ bias,
            __nv_bfloat16* __restrict__ oHi, __nv_bfloat16* __restrict__ oLo,
            float* __restrict__ oF,
            int Nreal, int Kstride, int doRelu, int mBlocks, int kLen, size_t partStride)
{
    extern __shared__ char smem[];
    const int rem = Nreal - blockIdx.x * NT;   // uniform across block
    if (rem >= 256)
        gemm_body<2, OUTFMT>(smem, aHi, aLo, wHi, wLo, bias, oHi, oLo, oF,
                             Nreal, Kstride, doRelu, mBlocks, kLen, partStride);
    else
        gemm_body<1, OUTFMT>(smem, aHi, aLo, wHi, wLo, bias, oHi, oLo, oF,
                             Nreal, Kstride, doRelu, mBlocks, kLen, partStride);
}

// ============================================================================
// Prepack kernels
// ============================================================================
#define CONCAT_BLOCKS 6144
#define W1_BLOCKS 1632              // 2176 rows x 192 / 256
__global__ void prep_fused(const float* __restrict__ state,
                           const float* __restrict__ pref,
                           __nv_bfloat16* __restrict__ xHi, __nv_bfloat16* __restrict__ xLo,
                           const float* __restrict__ w1,
                           __nv_bfloat16* __restrict__ w1Hi, __nv_bfloat16* __restrict__ w1Lo)
{
    if (blockIdx.x < CONCAT_BLOCKS) {
        int idx = blockIdx.x * blockDim.x + threadIdx.x;   // < 8192*192
        int b = idx / 192, c = idx - b * 192;
        float v = 0.0f;
        if (c < 128)      v = state[b * 128 + c];
        else if (c < 132) v = pref[b * 4 + (c - 128)];
        __nv_bfloat16 h = __float2bfloat16(v);
        xHi[idx] = h;
        xLo[idx] = __float2bfloat16(v - __bfloat162float(h));
    } else {
        int idx = (blockIdx.x - CONCAT_BLOCKS) * blockDim.x + threadIdx.x;  // < 2176*192
        int n = idx / 192, k = idx - n * 192;
        float v = (n < 2112 && k < 132) ? w1[n * 132 + k] : 0.0f;
        __nv_bfloat16 h = __float2bfloat16(v);
        w1Hi[idx] = h;
        w1Lo[idx] = __float2bfloat16(v - __bfloat162float(h));
    }
}

// N-pad via grid: rows >= Nrows write zeros (used for w5's 64 garbage rows)
__global__ void pad_rows_bf16pair(const float* __restrict__ W,
                                  __nv_bfloat16* __restrict__ hi,
                                  __nv_bfloat16* __restrict__ lo,
                                  int Nrows, int K)
{
    int n = blockIdx.x;
    const float4* src = reinterpret_cast<const float4*>(W + (size_t)n * K);
    uint2* dhi = reinterpret_cast<uint2*>(hi + (size_t)n * K);
    uint2* dlo = reinterpret_cast<uint2*>(lo + (size_t)n * K);
    int nv = K >> 2;
    bool valid = (n < Nrows);
    for (int i = threadIdx.x; i < nv; i += blockDim.x) {
        float4 v = valid ? src[i] : make_float4(0.f, 0.f, 0.f, 0.f);
        __nv_bfloat16 h0 = __float2bfloat16(v.x), h1 = __float2bfloat16(v.y);
        __nv_bfloat16 h2 = __float2bfloat16(v.z), h3 = __float2bfloat16(v.w);
        uint2 uh, ul;
        uh.x = (uint32_t)__bfloat16_as_ushort(h0) | ((uint32_t)__bfloat16_as_ushort(h1) << 16);
        uh.y = (uint32_t)__bfloat16_as_ushort(h2) | ((uint32_t)__bfloat16_as_ushort(h3) << 16);
        __nv_bfloat16 l0 = __float2bfloat16(v.x - __bfloat162float(h0));
        __nv_bfloat16 l1 = __float2bfloat16(v.y - __bfloat162float(h1));
        __nv_bfloat16 l2 = __float2bfloat16(v.z - __bfloat162float(h2));
        __nv_bfloat16 l3 = __float2bfloat16(v.w - __bfloat162float(h3));
        ul.x = (uint32_t)__bfloat16_as_ushort(l0) | ((uint32_t)__bfloat16_as_ushort(l1) << 16);
        ul.y = (uint32_t)__bfloat16_as_ushort(l2) | ((uint32_t)__bfloat16_as_ushort(l3) << 16);
        dhi[i] = uh;
        dlo[i] = ul;
    }
}

// ============================================================================
// envelope + L5 split-K combine
// ============================================================================
__global__ void envelope_combine_kernel(const float* __restrict__ qp,
                                        const float* __restrict__ bq,
                                        const float* __restrict__ pref,
                                        float* __restrict__ q,
                                        float* __restrict__ hq)
{
    int b = blockIdx.x * blockDim.x + threadIdx.x;
    if (b >= B_ROWS) return;
    const float* p0v = qp + (size_t)b * 64;
    const float* p1v = qp + (size_t)B_ROWS * 64 + (size_t)b * 64;
    float p0 = pref[b * 4 + 0], p1 = pref[b * 4 + 1];
    float p2 = pref[b * 4 + 2], p3 = pref[b * 4 + 3];
    float qv[64];
    #pragma unroll
    for (int j = 0; j < 64; j += 4) {
        float4 a = *reinterpret_cast<const float4*>(p0v + j);
        float4 c = *reinterpret_cast<const float4*>(p1v + j);
        qv[j + 0] = a.x + c.x + bq[j + 0];
        qv[j + 1] = a.y + c.y + bq[j + 1];
        qv[j + 2] = a.z + c.z + bq[j + 2];
        qv[j + 3] = a.w + c.w + bq[j + 3];
    }
    float best = -3.402823466e+38f;
    int ba = 0;
    #pragma unroll
    for (int a = 0; a < 16; a++) {
        float ip = qv[a * 4 + 0] * p0 + qv[a * 4 + 1] * p1
                 + qv[a * 4 + 2] * p2 + qv[a * 4 + 3] * p3;
        if (ip > best) { best = ip; ba = a; }
    }
    float* qrow = q + (size_t)b * 64;
    #pragma unroll
    for (int j = 0; j < 64; j += 4)
        *reinterpret_cast<float4*>(qrow + j) =
            make_float4(qv[j], qv[j + 1], qv[j + 2], qv[j + 3]);
    hq[b * 4 + 0] = qv[ba * 4 + 0];
    hq[b * 4 + 1] = qv[ba * 4 + 1];
    hq[b * 4 + 2] = qv[ba * 4 + 2];
    hq[b * 4 + 3] = qv[ba * 4 + 3];
}

// ============================================================================
// launch — launch #4 (ncu capture slot) = L2's GEMM
// ============================================================================
static inline void* sym(const void* s) { void* p; cudaGetSymbolAddress(&p, s); return p; }

extern "C" void kernel_launch(void* const* d_in, const int* in_sizes, int n_in,
                              void* d_out, int out_size)
{
    const float* state = (const float*)d_in[0];
    const float* pref  = (const float*)d_in[1];
    const float* w1 = (const float*)d_in[2];  const float* b1 = (const float*)d_in[3];
    const float* w2 = (const float*)d_in[4];  const float* b2 = (const float*)d_in[5];
    const float* w3 = (const float*)d_in[6];  const float* b3 = (const float*)d_in[7];
    const float* w4 = (const float*)d_in[8];  const float* b4 = (const float*)d_in[9];
    const float* wq = (const float*)d_in[10]; const float* bq = (const float*)d_in[11];

    float* out = (float*)d_out;
    float* hq = out;                       // [8192, 4]
    float* q  = out + (size_t)B_ROWS * 4;  // [8192, 64]

    __nv_bfloat16* xHi = (__nv_bfloat16*)sym(g_xHi);
    __nv_bfloat16* xLo = (__nv_bfloat16*)sym(g_xLo);
    __nv_bfloat16* w1Hi = (__nv_bfloat16*)sym(g_w1Hi); __nv_bfloat16* w1Lo = (__nv_bfloat16*)sym(g_w1Lo);
    __nv_bfloat16* w2Hi = (__nv_bfloat16*)sym(g_w2Hi); __nv_bfloat16* w2Lo = (__nv_bfloat16*)sym(g_w2Lo);
    __nv_bfloat16* w3Hi = (__nv_bfloat16*)sym(g_w3Hi); __nv_bfloat16* w3Lo = (__nv_bfloat16*)sym(g_w3Lo);
    __nv_bfloat16* w4Hi = (__nv_bfloat16*)sym(g_w4Hi); __nv_bfloat16* w4Lo = (__nv_bfloat16*)sym(g_w4Lo);
    __nv_bfloat16* w5Hi = (__nv_bfloat16*)sym(g_w5Hi); __nv_bfloat16* w5Lo = (__nv_bfloat16*)sym(g_w5Lo);
    __nv_bfloat16* aHi = (__nv_bfloat16*)sym(g_actAHi); __nv_bfloat16* aLo = (__nv_bfloat16*)sym(g_actALo);
    __nv_bfloat16* bHi = (__nv_bfloat16*)sym(g_actBHi); __nv_bfloat16* bLo = (__nv_bfloat16*)sym(g_actBLo);
    float* qp = (float*)sym(g_qpart);

    cudaFuncSetAttribute(gemm_bf16x3<0>, cudaFuncAttributeMaxDynamicSharedMemorySize, SMEM_TOTAL);
    cudaFuncSetAttribute(gemm_bf16x3<2>, cudaFuncAttributeMaxDynamicSharedMemorySize, SMEM_TOTAL);

    dim3 blk(GEMM_THREADS);

    // #1 fused concat + w1 prepack
    prep_fused<<<CONCAT_BLOCKS + W1_BLOCKS, 256>>>(state, pref, xHi, xLo, w1, w1Hi, w1Lo);
    // #2 w2 prepack
    pad_rows_bf16pair<<<4224, 256>>>(w2, w2Hi, w2Lo, 4224, 2112);
    // #3 L1: [8192,192] x [2112,192] -> actA (2112)
    gemm_bf16x3<0><<<dim3(9, 64), blk, SMEM_TOTAL>>>(
        xHi, xLo, w1Hi, w1Lo, b1, aHi, aLo, nullptr, 2112, 192, 1, 64, 192, 0);
    // #4 L2: [8192,2112] x [4224,2112] -> actB (4224)   <-- ncu capture slot
    gemm_bf16x3<0><<<dim3(17, 64), blk, SMEM_TOTAL>>>(
        aHi, aLo, w2Hi, w2Lo, b2, bHi, bLo, nullptr, 4224, 2112, 1, 64, 2112, 0);
    // #5 w3 prepack
    pad_rows_bf16pair<<<8448, 256>>>(w3, w3Hi, w3Lo, 8448, 4224);
    // #6 L3: [8192,4224] x [8448,4224] -> actA (8448)
    gemm_bf16x3<0><<<dim3(33, 64), blk, SMEM_TOTAL>>>(
        bHi, bLo, w3Hi, w3Lo, b3, aHi, aLo, nullptr, 8448, 4224, 1, 64, 4224, 0);
    // #7 w4 prepack
    pad_rows_bf16pair<<<4224, 256>>>(w4, w4Hi, w4Lo, 4224, 8448);
    // #8 L4: [8192,8448] x [4224,8448] -> actB (4224)
    gemm_bf16x3<0><<<dim3(17, 64), blk, SMEM_TOTAL>>>(
        aHi, aLo, w4Hi, w4Lo, b4, bHi, bLo, nullptr, 4224, 8448, 1, 64, 8448, 0);
    // #9 w5 prepack (128 rows: 64 real + 64 zero-padded)
    pad_rows_bf16pair<<<128, 256>>>(wq, w5Hi, w5Lo, 64, 4224);
    // #10 L5 split-K: [8192,4224] x [64,4224] -> 2 raw partials (no bias)
    gemm_bf16x3<2><<<dim3(1, 128), blk, SMEM_TOTAL>>>(
        bHi, bLo, w5Hi, w5Lo, nullptr, nullptr, nullptr, qp,
        64, 4224, 0, 64, 2112, (size_t)B_ROWS * 64);
    // #11 combine + envelope
    envelope_combine_kernel<<<(B_ROWS + 255) / 256, 256>>>(qp, bq, pref, q, hq);
}

// round 11
// speedup vs baseline: 1.0329x; 1.0329x over previous
#include <cuda_runtime.h>
#include <cuda_bf16.h>
#include <cstdint>

// ============================================================================
// Problem constants
// ============================================================================
#define B_ROWS 8192

#define MT 128
#define NT 256
#define KC 64
#define GEMM_THREADS 256

#define STG_A_HI 0
#define STG_A_LO 16384
#define STG_W_HI 32768
#define STG_W_LO 65536
#define STAGE_BYTES 98304          // 96 KB
#define SMEM_TOTAL (2 * STAGE_BYTES)

// ============================================================================
// Scratch (__device__ globals; no cudaMalloc allowed)
// ============================================================================
__device__ __nv_bfloat16 g_xHi[B_ROWS * 192];
__device__ __nv_bfloat16 g_xLo[B_ROWS * 192];

__device__ __nv_bfloat16 g_w1Hi[2112 * 192],           g_w1Lo[2112 * 192];
__device__ __nv_bfloat16 g_w2Hi[(size_t)4224 * 2112],  g_w2Lo[(size_t)4224 * 2112];
__device__ __nv_bfloat16 g_w3Hi[(size_t)8448 * 4224],  g_w3Lo[(size_t)8448 * 4224];
__device__ __nv_bfloat16 g_w4Hi[(size_t)4224 * 8448],  g_w4Lo[(size_t)4224 * 8448];
__device__ __nv_bfloat16 g_w5Hi[64 * 4224],            g_w5Lo[64 * 4224];

__device__ __nv_bfloat16 g_actAHi[(size_t)B_ROWS * 8448], g_actALo[(size_t)B_ROWS * 8448];
__device__ __nv_bfloat16 g_actBHi[(size_t)B_ROWS * 4224], g_actBLo[(size_t)B_ROWS * 4224];

// L5 split-K partials: 2 x [8192, 64] fp32
__device__ __align__(16) float g_qpart[2 * B_ROWS * 64];

// ============================================================================
// PTX helpers
// ============================================================================
__device__ __forceinline__ uint32_t smem_u32(const void* p) {
    uint32_t a;
    asm("{ .reg .u64 t; cvta.to.shared.u64 t, %1; cvt.u32.u64 %0, t; }"
        : "=r"(a) : "l"(p));
    return a;
}

#define CP_ASYNC16(dst, src) \
    asm volatile("cp.async.cg.shared.global [%0], [%1], 16;" :: "r"(dst), "l"(src))

#define CP_COMMIT() asm volatile("cp.async.commit_group;" ::: "memory")
#define CP_WAIT(n)  asm volatile("cp.async.wait_group %0;" :: "n"(n) : "memory")

#define LDSM4(r, addr) \
    asm volatile("ldmatrix.sync.aligned.m8n8.x4.shared.b16 {%0,%1,%2,%3}, [%4];" \
                 : "=r"((r)[0]), "=r"((r)[1]), "=r"((r)[2]), "=r"((r)[3]) : "r"(addr))

#define MMA_BF16(d, a, b0, b1) \
    asm volatile("mma.sync.aligned.m16n8k16.row.col.f32.bf16.bf16.f32 " \
                 "{%0,%1,%2,%3},{%4,%5,%6,%7},{%8,%9},{%0,%1,%2,%3};" \
                 : "+f"((d)[0]), "+f"((d)[1]), "+f"((d)[2]), "+f"((d)[3]) \
                 : "r"((a)[0]), "r"((a)[1]), "r"((a)[2]), "r"((a)[3]), \
                   "r"(b0), "r"(b1))

__device__ __forceinline__ uint32_t swz(int r, int c) {
    return (uint32_t)(r * 128 + ((c ^ (r & 7)) << 4));
}

// split one fp32 row into hi/lo bf16 (vectorized); valid=false writes zeros
__device__ __forceinline__ void split_row(const float* __restrict__ src,
                                          __nv_bfloat16* __restrict__ hi,
                                          __nv_bfloat16* __restrict__ lo,
                                          int K, bool valid)
{
    const float4* s4 = reinterpret_cast<const float4*>(src);
    uint2* dhi = reinterpret_cast<uint2*>(hi);
    uint2* dlo = reinterpret_cast<uint2*>(lo);
    int nv = K >> 2;
    for (int i = threadIdx.x; i < nv; i += blockDim.x) {
        float4 v = valid ? s4[i] : make_float4(0.f, 0.f, 0.f, 0.f);
        __nv_bfloat16 h0 = __float2bfloat16(v.x), h1 = __float2bfloat16(v.y);
        __nv_bfloat16 h2 = __float2bfloat16(v.z), h3 = __float2bfloat16(v.w);
        uint2 uh, ul;
        uh.x = (uint32_t)__bfloat16_as_ushort(h0) | ((uint32_t)__bfloat16_as_ushort(h1) << 16);
        uh.y = (uint32_t)__bfloat16_as_ushort(h2) | ((uint32_t)__bfloat16_as_ushort(h3) << 16);
        __nv_bfloat16 l0 = __float2bfloat16(v.x - __bfloat162float(h0));
        __nv_bfloat16 l1 = __float2bfloat16(v.y - __bfloat162float(h1));
        __nv_bfloat16 l2 = __float2bfloat16(v.z - __bfloat162float(h2));
        __nv_bfloat16 l3 = __float2bfloat16(v.w - __bfloat162float(h3));
        ul.x = (uint32_t)__bfloat16_as_ushort(l0) | ((uint32_t)__bfloat16_as_ushort(l1) << 16);
        ul.y = (uint32_t)__bfloat16_as_ushort(l2) | ((uint32_t)__bfloat16_as_ushort(l3) << 16);
        dhi[i] = uh;
        dlo[i] = ul;
    }
}

// ============================================================================
// GEMM body (R7/R9 proven config: 256 threads, 2-stage KC=64 double buffer).
// Split-K: part p of grid.y handles kLen K-columns at offset p*kLen.
// NPT: n p-tiles per warp. OUTFMT 0: bf16 hi/lo pair, 2: fp32 (bias nullable).
// ============================================================================
template<int NPT, int OUTFMT>
__device__ __forceinline__ void gemm_body(
    char* smem,
    const __nv_bfloat16* __restrict__ aHi, const __nv_bfloat16* __restrict__ aLo,
    const __nv_bfloat16* __restrict__ wHi, const __nv_bfloat16* __restrict__ wLo,
    const float* __restrict__ bias,
    __nv_bfloat16* __restrict__ oHi, __nv_bfloat16* __restrict__ oLo,
    float* __restrict__ oF,
    int Nreal, int Kstride, int doRelu, int mBlocks, int kLen, size_t partStride)
{
    const uint32_t sb = smem_u32(smem);
    const int tid  = threadIdx.x;
    const int wid  = tid >> 5;
    const int lane = tid & 31;
    const int by   = blockIdx.y;
    const int part = by / mBlocks;
    const int m0 = (by - part * mBlocks) * MT;
    const int n0 = blockIdx.x * NT;
    const int kOff = part * kLen;
    aHi += kOff; aLo += kOff; wHi += kOff; wLo += kOff;
    if (OUTFMT == 2) oF += (size_t)part * partStride;
    const int nChunks = kLen / KC;

    auto load_chunk = [&](int c, int stage) {
        const uint32_t base = sb + stage * STAGE_BYTES;
        const int k0 = c * KC;
        #pragma unroll
        for (int i = 0; i < 4; i++) {                    // A: 1024 x 16B
            int j = tid + i * GEMM_THREADS;
            int r = j >> 3, cc = j & 7;
            uint32_t d = base + swz(r, cc);
            size_t so = (size_t)(m0 + r) * Kstride + k0 + cc * 8;
            CP_ASYNC16(d + STG_A_HI, aHi + so);
            CP_ASYNC16(d + STG_A_LO, aLo + so);
        }
        #pragma unroll
        for (int i = 0; i < 2 * NPT; i++) {              // W: NPT*64 rows x 8 x 16B
            int j = tid + i * GEMM_THREADS;
            int r = j >> 3, cc = j & 7;
            uint32_t d = base + swz(r, cc);
            size_t so = (size_t)(n0 + r) * Kstride + k0 + cc * 8;
            CP_ASYNC16(d + STG_W_HI, wHi + so);
            CP_ASYNC16(d + STG_W_LO, wLo + so);
        }
    };

    float acc[4][2 * NPT][4];
    #pragma unroll
    for (int t = 0; t < 4; t++)
        #pragma unroll
        for (int nf = 0; nf < 2 * NPT; nf++)
            #pragma unroll
            for (int e = 0; e < 4; e++) acc[t][nf][e] = 0.0f;

    const int mBase = (wid & 1) * 64;
    const int nBase = (wid >> 1) * (NPT * 16);

    load_chunk(0, 0);
    CP_COMMIT();

    for (int c = 0; c < nChunks; c++) {
        if (c + 1 < nChunks) {
            load_chunk(c + 1, (c + 1) & 1);
            CP_COMMIT();
            CP_WAIT(1);
        } else {
            CP_WAIT(0);
        }
        __syncthreads();

        const uint32_t base = sb + (c & 1) * STAGE_BYTES;
        #pragma unroll
        for (int s = 0; s < 4; s++) {
            uint32_t aH[4][4], aL[4][4];
            #pragma unroll
            for (int t = 0; t < 4; t++) {
                int row = mBase + t * 16 + (lane & 15);
                int c16 = s * 2 + (lane >> 4);
                uint32_t ad = base + swz(row, c16);
                LDSM4(aH[t], ad + STG_A_HI);
                LDSM4(aL[t], ad + STG_A_LO);
            }
            #pragma unroll
            for (int p = 0; p < NPT; p++) {
                int g = lane >> 3;
                int row = nBase + p * 16 + (lane & 7) + ((g >> 1) << 3);
                int c16 = s * 2 + (g & 1);
                uint32_t wd = base + swz(row, c16);
                uint32_t bH[4], bL[4];
                LDSM4(bH, wd + STG_W_HI);
                LDSM4(bL, wd + STG_W_LO);
                #pragma unroll
                for (int t = 0; t < 4; t++) {
                    MMA_BF16(acc[t][2 * p],     aH[t], bH[0], bH[1]);
                    MMA_BF16(acc[t][2 * p + 1], aH[t], bH[2], bH[3]);
                }
                #pragma unroll
                for (int t = 0; t < 4; t++) {
                    MMA_BF16(acc[t][2 * p],     aL[t], bH[0], bH[1]);
                    MMA_BF16(acc[t][2 * p + 1], aL[t], bH[2], bH[3]);
                }
                #pragma unroll
                for (int t = 0; t < 4; t++) {
                    MMA_BF16(acc[t][2 * p],     aH[t], bL[0], bL[1]);
                    MMA_BF16(acc[t][2 * p + 1], aH[t], bL[2], bL[3]);
                }
            }
        }
        __syncthreads();
    }

    // ---------------- epilogue ---------------------------------------------
    const int mW = m0 + mBase;
    const int nW = n0 + nBase;
    #pragma unroll
    for (int t = 0; t < 4; t++) {
        #pragma unroll
        for (int nf = 0; nf < 2 * NPT; nf++) {
            int cc = nW + nf * 8 + ((lane & 3) << 1);
            if (cc >= Nreal) continue;
            int r0 = mW + t * 16 + (lane >> 2);
            int r1 = r0 + 8;
            float bv0 = bias ? bias[cc] : 0.0f;
            float bv1 = bias ? bias[cc + 1] : 0.0f;
            float v00 = acc[t][nf][0] + bv0;
            float v01 = acc[t][nf][1] + bv1;
            float v10 = acc[t][nf][2] + bv0;
            float v11 = acc[t][nf][3] + bv1;
            if (doRelu) {
                v00 = fmaxf(v00, 0.f); v01 = fmaxf(v01, 0.f);
                v10 = fmaxf(v10, 0.f); v11 = fmaxf(v11, 0.f);
            }
            if constexpr (OUTFMT == 2) {
                *reinterpret_cast<float2*>(oF + (size_t)r0 * Nreal + cc) = make_float2(v00, v01);
                *reinterpret_cast<float2*>(oF + (size_t)r1 * Nreal + cc) = make_float2(v10, v11);
            } else {
                __nv_bfloat16 h00 = __float2bfloat16(v00), h01 = __float2bfloat16(v01);
                __nv_bfloat16 h10 = __float2bfloat16(v10), h11 = __float2bfloat16(v11);
                __nv_bfloat16 l00 = __float2bfloat16(v00 - __bfloat162float(h00));
                __nv_bfloat16 l01 = __float2bfloat16(v01 - __bfloat162float(h01));
                __nv_bfloat16 l10 = __float2bfloat16(v10 - __bfloat162float(h10));
                __nv_bfloat16 l11 = __float2bfloat16(v11 - __bfloat162float(h11));
                *reinterpret_cast<__nv_bfloat162*>(oHi + (size_t)r0 * Nreal + cc) = __nv_bfloat162(h00, h01);
                *reinterpret_cast<__nv_bfloat162*>(oHi + (size_t)r1 * Nreal + cc) = __nv_bfloat162(h10, h11);
                *reinterpret_cast<__nv_bfloat162*>(oLo + (size_t)r0 * Nreal + cc) = __nv_bfloat162(l00, l01);
                *reinterpret_cast<__nv_bfloat162*>(oLo + (size_t)r1 * Nreal + cc) = __nv_bfloat162(l10, l11);
            }
        }
    }
}

// ============================================================================
// Fused kernel: z=0 blocks do the GEMM for layer i; z=1 blocks (dispatched
// last) prepack layer i+1's weights into hi/lo bf16 during the drain tail.
// Safe: layer i never reads prep outputs; layer i+1 is a later launch.
// ============================================================================
template<int OUTFMT>
__global__ void __launch_bounds__(GEMM_THREADS, 1)
gemm_bf16x3(const __nv_bfloat16* __restrict__ aHi, const __nv_bfloat16* __restrict__ aLo,
            const __nv_bfloat16* __restrict__ wHi, const __nv_bfloat16* __restrict__ wLo,
            const float* __restrict__ bias,
            __nv_bfloat16* __restrict__ oHi, __nv_bfloat16* __restrict__ oLo,
            float* __restrict__ oF,
            int Nreal, int Kstride, int doRelu, int mBlocks, int kLen, size_t partStride,
            const float* __restrict__ prepW,
            __nv_bfloat16* __restrict__ prepHi, __nv_bfloat16* __restrict__ prepLo,
            int prepRows, int prepK)
{
    if (blockIdx.z == 1) {
        // -------- prepack branch (runs in the GEMM's drain tail) ----------
        int nBlocks = gridDim.x * gridDim.y;
        int lb = blockIdx.y * gridDim.x + blockIdx.x;
        for (int n = lb; n < prepRows; n += nBlocks) {
            split_row(prepW + (size_t)n * prepK,
                      prepHi + (size_t)n * prepK,
                      prepLo + (size_t)n * prepK, prepK, true);
        }
        return;
    }
    extern __shared__ char smem[];
    const int rem = Nreal - blockIdx.x * NT;   // uniform across block
    if (rem >= 256)
        gemm_body<4, OUTFMT>(smem, aHi, aLo, wHi, wLo, bias, oHi, oLo, oF,
                             Nreal, Kstride, doRelu, mBlocks, kLen, partStride);
    else if (rem >= 128)
        gemm_body<2, OUTFMT>(smem, aHi, aLo, wHi, wLo, bias, oHi, oLo, oF,
                             Nreal, Kstride, doRelu, mBlocks, kLen, partStride);
    else
        gemm_body<1, OUTFMT>(smem, aHi, aLo, wHi, wLo, bias, oHi, oLo, oF,
                             Nreal, Kstride, doRelu, mBlocks, kLen, partStride);
}

// ============================================================================
// Prepack: fused concat-split (x) + w1 split-pad-K (needed before L1 itself)
// ============================================================================
#define CONCAT_BLOCKS 6144
#define W1_BLOCKS 1584
__global__ void prep_fused(const float* __restrict__ state,
                           const float* __restrict__ pref,
                           __nv_bfloat16* __restrict__ xHi, __nv_bfloat16* __restrict__ xLo,
                           const float* __restrict__ w1,
                           __nv_bfloat16* __restrict__ w1Hi, __nv_bfloat16* __restrict__ w1Lo)
{
    if (blockIdx.x < CONCAT_BLOCKS) {
        int idx = blockIdx.x * blockDim.x + threadIdx.x;   // < 8192*192
        int b = idx / 192, c = idx - b * 192;
        float v = 0.0f;
        if (c < 128)      v = state[b * 128 + c];
        else if (c < 132) v = pref[b * 4 + (c - 128)];
        __nv_bfloat16 h = __float2bfloat16(v);
        xHi[idx] = h;
        xLo[idx] = __float2bfloat16(v - __bfloat162float(h));
    } else {
        int idx = (blockIdx.x - CONCAT_BLOCKS) * blockDim.x + threadIdx.x;  // < 2112*192
        int n = idx / 192, k = idx - n * 192;
        float v = (k < 132) ? w1[n * 132 + k] : 0.0f;
        __nv_bfloat16 h = __float2bfloat16(v);
        w1Hi[idx] = h;
        w1Lo[idx] = __float2bfloat16(v - __bfloat162float(h));
    }
}

// ============================================================================
// envelope + L5 split-K combine
// ============================================================================
__global__ void envelope_combine_kernel(const float* __restrict__ qp,
                                        const float* __restrict__ bq,
                                        const float* __restrict__ pref,
                                        float* __restrict__ q,
                                        float* __restrict__ hq)
{
    int b = blockIdx.x * blockDim.x + threadIdx.x;
    if (b >= B_ROWS) return;
    const float* p0v = qp + (size_t)b * 64;
    const float* p1v = qp + (size_t)B_ROWS * 64 + (size_t)b * 64;
    float p0 = pref[b * 4 + 0], p1 = pref[b * 4 + 1];
    float p2 = pref[b * 4 + 2], p3 = pref[b * 4 + 3];
    float qv[64];
    #pragma unroll
    for (int j = 0; j < 64; j += 4) {
        float4 a = *reinterpret_cast<const float4*>(p0v + j);
        float4 c = *reinterpret_cast<const float4*>(p1v + j);
        qv[j + 0] = a.x + c.x + bq[j + 0];
        qv[j + 1] = a.y + c.y + bq[j + 1];
        qv[j + 2] = a.z + c.z + bq[j + 2];
        qv[j + 3] = a.w + c.w + bq[j + 3];
    }
    float best = -3.402823466e+38f;
    int ba = 0;
    #pragma unroll
    for (int a = 0; a < 16; a++) {
        float ip = qv[a * 4 + 0] * p0 + qv[a * 4 + 1] * p1
                 + qv[a * 4 + 2] * p2 + qv[a * 4 + 3] * p3;
        if (ip > best) { best = ip; ba = a; }
    }
    float* qrow = q + (size_t)b * 64;
    #pragma unroll
    for (int j = 0; j < 64; j += 4)
        *reinterpret_cast<float4*>(qrow + j) =
            make_float4(qv[j], qv[j + 1], qv[j + 2], qv[j + 3]);
    hq[b * 4 + 0] = qv[ba * 4 + 0];
    hq[b * 4 + 1] = qv[ba * 4 + 1];
    hq[b * 4 + 2] = qv[ba * 4 + 2];
    hq[b * 4 + 3] = qv[ba * 4 + 3];
}

// ============================================================================
// launch — #4 (ncu capture slot) = L3 fused GEMM
// ============================================================================
static inline void* sym(const void* s) { void* p; cudaGetSymbolAddress(&p, s); return p; }

extern "C" void kernel_launch(void* const* d_in, const int* in_sizes, int n_in,
                              void* d_out, int out_size)
{
    const float* state = (const float*)d_in[0];
    const float* pref  = (const float*)d_in[1];
    const float* w1 = (const float*)d_in[2];  const float* b1 = (const float*)d_in[3];
    const float* w2 = (const float*)d_in[4];  const float* b2 = (const float*)d_in[5];
    const float* w3 = (const float*)d_in[6];  const float* b3 = (const float*)d_in[7];
    const float* w4 = (const float*)d_in[8];  const float* b4 = (const float*)d_in[9];
    const float* wq = (const float*)d_in[10]; const float* bq = (const float*)d_in[11];

    float* out = (float*)d_out;
    float* hq = out;                       // [8192, 4]
    float* q  = out + (size_t)B_ROWS * 4;  // [8192, 64]

    __nv_bfloat16* xHi = (__nv_bfloat16*)sym(g_xHi);
    __nv_bfloat16* xLo = (__nv_bfloat16*)sym(g_xLo);
    __nv_bfloat16* w1Hi = (__nv_bfloat16*)sym(g_w1Hi); __nv_bfloat16* w1Lo = (__nv_bfloat16*)sym(g_w1Lo);
    __nv_bfloat16* w2Hi = (__nv_bfloat16*)sym(g_w2Hi); __nv_bfloat16* w2Lo = (__nv_bfloat16*)sym(g_w2Lo);
    __nv_bfloat16* w3Hi = (__nv_bfloat16*)sym(g_w3Hi); __nv_bfloat16* w3Lo = (__nv_bfloat16*)sym(g_w3Lo);
    __nv_bfloat16* w4Hi = (__nv_bfloat16*)sym(g_w4Hi); __nv_bfloat16* w4Lo = (__nv_bfloat16*)sym(g_w4Lo);
    __nv_bfloat16* w5Hi = (__nv_bfloat16*)sym(g_w5Hi); __nv_bfloat16* w5Lo = (__nv_bfloat16*)sym(g_w5Lo);
    __nv_bfloat16* aHi = (__nv_bfloat16*)sym(g_actAHi); __nv_bfloat16* aLo = (__nv_bfloat16*)sym(g_actALo);
    __nv_bfloat16* bHi = (__nv_bfloat16*)sym(g_actBHi); __nv_bfloat16* bLo = (__nv_bfloat16*)sym(g_actBLo);
    float* qp = (float*)sym(g_qpart);

    cudaFuncSetAttribute(gemm_bf16x3<0>, cudaFuncAttributeMaxDynamicSharedMemorySize, SMEM_TOTAL);
    cudaFuncSetAttribute(gemm_bf16x3<2>, cudaFuncAttributeMaxDynamicSharedMemorySize, SMEM_TOTAL);

    dim3 blk(GEMM_THREADS);

    // #1 concat + w1 prepack (needed by L1 itself — must precede it)
    prep_fused<<<CONCAT_BLOCKS + W1_BLOCKS, 256>>>(state, pref, xHi, xLo, w1, w1Hi, w1Lo);
    // #2 L1 (+ w2 prepack in tail): [8192,192] x [2112,192] -> actA (2112)
    gemm_bf16x3<0><<<dim3(9, 64, 2), blk, SMEM_TOTAL>>>(
        xHi, xLo, w1Hi, w1Lo, b1, aHi, aLo, nullptr, 2112, 192, 1, 64, 192, 0,
        w2, w2Hi, w2Lo, 4224, 2112);
    // #3 L2 (+ w3 prepack): [8192,2112] x [4224,2112] -> actB (4224)
    gemm_bf16x3<0><<<dim3(17, 64, 2), blk, SMEM_TOTAL>>>(
        aHi, aLo, w2Hi, w2Lo, b2, bHi, bLo, nullptr, 4224, 2112, 1, 64, 2112, 0,
        w3, w3Hi, w3Lo, 8448, 4224);
    // #4 L3 (+ w4 prepack): [8192,4224] x [8448,4224] -> actA (8448)   <-- ncu slot
    gemm_bf16x3<0><<<dim3(33, 64, 2), blk, SMEM_TOTAL>>>(
        bHi, bLo, w3Hi, w3Lo, b3, aHi, aLo, nullptr, 8448, 4224, 1, 64, 4224, 0,
        w4, w4Hi, w4Lo, 4224, 8448);
    // #5 L4 (+ w5 prepack): [8192,8448] x [4224,8448] -> actB (4224)
    gemm_bf16x3<0><<<dim3(17, 64, 2), blk, SMEM_TOTAL>>>(
        aHi, aLo, w4Hi, w4Lo, b4, bHi, bLo, nullptr, 4224, 8448, 1, 64, 8448, 0,
        wq, w5Hi, w5Lo, 64, 4224);
    // #6 L5 split-K: [8192,4224] x [64,4224] -> 2 raw partials (no bias)
    gemm_bf16x3<2><<<dim3(1, 128, 1), blk, SMEM_TOTAL>>>(
        bHi, bLo, w5Hi, w5Lo, nullptr, nullptr, nullptr, qp,
        64, 4224, 0, 64, 2112, (size_t)B_ROWS * 64,
        nullptr, nullptr, nullptr, 0, 0);
    // #7 combine + envelope
    envelope_combine_kernel<<<(B_ROWS + 255) / 256, 256>>>(qp, bq, pref, q, hq);
}

// round 12
// speedup vs baseline: 1.0441x; 1.0108x over previous
#include <cuda_runtime.h>
#include <cuda_bf16.h>
#include <cstdint>

// ============================================================================
// Problem constants
// ============================================================================
#define B_ROWS 8192

#define MT 128
#define NT 256
#define KC 64
#define GEMM_THREADS 256

#define STG_A_HI 0
#define STG_A_LO 16384
#define STG_W_HI 32768
#define STG_W_LO 65536
#define STAGE_BYTES 98304          // 96 KB
#define SMEM_TOTAL (2 * STAGE_BYTES)

// ============================================================================
// Scratch (__device__ globals; no cudaMalloc allowed)
// ============================================================================
__device__ __nv_bfloat16 g_xHi[B_ROWS * 192];
__device__ __nv_bfloat16 g_xLo[B_ROWS * 192];

__device__ __nv_bfloat16 g_w1Hi[2112 * 192],           g_w1Lo[2112 * 192];
__device__ __nv_bfloat16 g_w2Hi[(size_t)4224 * 2112],  g_w2Lo[(size_t)4224 * 2112];
__device__ __nv_bfloat16 g_w3Hi[(size_t)8448 * 4224],  g_w3Lo[(size_t)8448 * 4224];
__device__ __nv_bfloat16 g_w4Hi[(size_t)4224 * 8448],  g_w4Lo[(size_t)4224 * 8448];
__device__ __nv_bfloat16 g_w5Hi[64 * 4224],            g_w5Lo[64 * 4224];

__device__ __nv_bfloat16 g_actAHi[(size_t)B_ROWS * 8448], g_actALo[(size_t)B_ROWS * 8448];
__device__ __nv_bfloat16 g_actBHi[(size_t)B_ROWS * 4224], g_actBLo[(size_t)B_ROWS * 4224];

// L5 split-K partials: 2 x [8192, 64] fp32
__device__ __align__(16) float g_qpart[2 * B_ROWS * 64];

// ============================================================================
// PTX helpers
// ============================================================================
__device__ __forceinline__ uint32_t smem_u32(const void* p) {
    uint32_t a;
    asm("{ .reg .u64 t; cvta.to.shared.u64 t, %1; cvt.u32.u64 %0, t; }"
        : "=r"(a) : "l"(p));
    return a;
}

#define CP_ASYNC16(dst, src) \
    asm volatile("cp.async.cg.shared.global [%0], [%1], 16;" :: "r"(dst), "l"(src))

#define CP_COMMIT() asm volatile("cp.async.commit_group;" ::: "memory")
#define CP_WAIT(n)  asm volatile("cp.async.wait_group %0;" :: "n"(n) : "memory")

#define LDSM4(r, addr) \
    asm volatile("ldmatrix.sync.aligned.m8n8.x4.shared.b16 {%0,%1,%2,%3}, [%4];" \
                 : "=r"((r)[0]), "=r"((r)[1]), "=r"((r)[2]), "=r"((r)[3]) : "r"(addr))

#define MMA_BF16(d, a, b0, b1) \
    asm volatile("mma.sync.aligned.m16n8k16.row.col.f32.bf16.bf16.f32 " \
                 "{%0,%1,%2,%3},{%4,%5,%6,%7},{%8,%9},{%0,%1,%2,%3};" \
                 : "+f"((d)[0]), "+f"((d)[1]), "+f"((d)[2]), "+f"((d)[3]) \
                 : "r"((a)[0]), "r"((a)[1]), "r"((a)[2]), "r"((a)[3]), \
                   "r"(b0), "r"(b1))

__device__ __forceinline__ uint32_t swz(int r, int c) {
    return (uint32_t)(r * 128 + ((c ^ (r & 7)) << 4));
}

// split one fp32 row into hi/lo bf16 (vectorized across the CTA's threads)
__device__ __forceinline__ void split_row(const float* __restrict__ src,
                                          __nv_bfloat16* __restrict__ hi,
                                          __nv_bfloat16* __restrict__ lo,
                                          int K)
{
    const float4* s4 = reinterpret_cast<const float4*>(src);
    uint2* dhi = reinterpret_cast<uint2*>(hi);
    uint2* dlo = reinterpret_cast<uint2*>(lo);
    int nv = K >> 2;
    for (int i = threadIdx.x; i < nv; i += GEMM_THREADS) {
        float4 v = s4[i];
        __nv_bfloat16 h0 = __float2bfloat16(v.x), h1 = __float2bfloat16(v.y);
        __nv_bfloat16 h2 = __float2bfloat16(v.z), h3 = __float2bfloat16(v.w);
        uint2 uh, ul;
        uh.x = (uint32_t)__bfloat16_as_ushort(h0) | ((uint32_t)__bfloat16_as_ushort(h1) << 16);
        uh.y = (uint32_t)__bfloat16_as_ushort(h2) | ((uint32_t)__bfloat16_as_ushort(h3) << 16);
        __nv_bfloat16 l0 = __float2bfloat16(v.x - __bfloat162float(h0));
        __nv_bfloat16 l1 = __float2bfloat16(v.y - __bfloat162float(h1));
        __nv_bfloat16 l2 = __float2bfloat16(v.z - __bfloat162float(h2));
        __nv_bfloat16 l3 = __float2bfloat16(v.w - __bfloat162float(h3));
        ul.x = (uint32_t)__bfloat16_as_ushort(l0) | ((uint32_t)__bfloat16_as_ushort(l1) << 16);
        ul.y = (uint32_t)__bfloat16_as_ushort(l2) | ((uint32_t)__bfloat16_as_ushort(l3) << 16);
        dhi[i] = uh;
        dlo[i] = ul;
    }
}

// ============================================================================
// GEMM body (R7/R9 proven config: 256 threads, 2-stage KC=64 double buffer).
// Split-K: part p of grid.y handles kLen K-columns at offset p*kLen.
// NPT: n p-tiles per warp. OUTFMT 0: bf16 hi/lo pair, 2: fp32 (bias nullable).
// ============================================================================
template<int NPT, int OUTFMT>
__device__ __forceinline__ void gemm_body(
    char* smem,
    const __nv_bfloat16* __restrict__ aHi, const __nv_bfloat16* __restrict__ aLo,
    const __nv_bfloat16* __restrict__ wHi, const __nv_bfloat16* __restrict__ wLo,
    const float* __restrict__ bias,
    __nv_bfloat16* __restrict__ oHi, __nv_bfloat16* __restrict__ oLo,
    float* __restrict__ oF,
    int Nreal, int Kstride, int doRelu, int mBlocks, int kLen, size_t partStride)
{
    const uint32_t sb = smem_u32(smem);
    const int tid  = threadIdx.x;
    const int wid  = tid >> 5;
    const int lane = tid & 31;
    const int by   = blockIdx.y;
    const int part = by / mBlocks;
    const int m0 = (by - part * mBlocks) * MT;
    const int n0 = blockIdx.x * NT;
    const int kOff = part * kLen;
    aHi += kOff; aLo += kOff; wHi += kOff; wLo += kOff;
    if (OUTFMT == 2) oF += (size_t)part * partStride;
    const int nChunks = kLen / KC;

    auto load_chunk = [&](int c, int stage) {
        const uint32_t base = sb + stage * STAGE_BYTES;
        const int k0 = c * KC;
        #pragma unroll
        for (int i = 0; i < 4; i++) {                    // A: 1024 x 16B
            int j = tid + i * GEMM_THREADS;
            int r = j >> 3, cc = j & 7;
            uint32_t d = base + swz(r, cc);
            size_t so = (size_t)(m0 + r) * Kstride + k0 + cc * 8;
            CP_ASYNC16(d + STG_A_HI, aHi + so);
            CP_ASYNC16(d + STG_A_LO, aLo + so);
        }
        #pragma unroll
        for (int i = 0; i < 2 * NPT; i++) {              // W: NPT*64 rows x 8 x 16B
            int j = tid + i * GEMM_THREADS;
            int r = j >> 3, cc = j & 7;
            uint32_t d = base + swz(r, cc);
            size_t so = (size_t)(n0 + r) * Kstride + k0 + cc * 8;
            CP_ASYNC16(d + STG_W_HI, wHi + so);
            CP_ASYNC16(d + STG_W_LO, wLo + so);
        }
    };

    float acc[4][2 * NPT][4];
    #pragma unroll
    for (int t = 0; t < 4; t++)
        #pragma unroll
        for (int nf = 0; nf < 2 * NPT; nf++)
            #pragma unroll
            for (int e = 0; e < 4; e++) acc[t][nf][e] = 0.0f;

    const int mBase = (wid & 1) * 64;
    const int nBase = (wid >> 1) * (NPT * 16);

    load_chunk(0, 0);
    CP_COMMIT();

    for (int c = 0; c < nChunks; c++) {
        if (c + 1 < nChunks) {
            load_chunk(c + 1, (c + 1) & 1);
            CP_COMMIT();
            CP_WAIT(1);
        } else {
            CP_WAIT(0);
        }
        __syncthreads();

        const uint32_t base = sb + (c & 1) * STAGE_BYTES;
        #pragma unroll
        for (int s = 0; s < 4; s++) {
            uint32_t aH[4][4], aL[4][4];
            #pragma unroll
            for (int t = 0; t < 4; t++) {
                int row = mBase + t * 16 + (lane & 15);
                int c16 = s * 2 + (lane >> 4);
                uint32_t ad = base + swz(row, c16);
                LDSM4(aH[t], ad + STG_A_HI);
                LDSM4(aL[t], ad + STG_A_LO);
            }
            #pragma unroll
            for (int p = 0; p < NPT; p++) {
                int g = lane >> 3;
                int row = nBase + p * 16 + (lane & 7) + ((g >> 1) << 3);
                int c16 = s * 2 + (g & 1);
                uint32_t wd = base + swz(row, c16);
                uint32_t bH[4], bL[4];
                LDSM4(bH, wd + STG_W_HI);
                LDSM4(bL, wd + STG_W_LO);
                #pragma unroll
                for (int t = 0; t < 4; t++) {
                    MMA_BF16(acc[t][2 * p],     aH[t], bH[0], bH[1]);
                    MMA_BF16(acc[t][2 * p + 1], aH[t], bH[2], bH[3]);
                }
                #pragma unroll
                for (int t = 0; t < 4; t++) {
                    MMA_BF16(acc[t][2 * p],     aL[t], bH[0], bH[1]);
                    MMA_BF16(acc[t][2 * p + 1], aL[t], bH[2], bH[3]);
                }
                #pragma unroll
                for (int t = 0; t < 4; t++) {
                    MMA_BF16(acc[t][2 * p],     aH[t], bL[0], bL[1]);
                    MMA_BF16(acc[t][2 * p + 1], aH[t], bL[2], bL[3]);
                }
            }
        }
        __syncthreads();
    }

    // ---------------- epilogue ---------------------------------------------
    const int mW = m0 + mBase;
    const int nW = n0 + nBase;
    #pragma unroll
    for (int t = 0; t < 4; t++) {
        #pragma unroll
        for (int nf = 0; nf < 2 * NPT; nf++) {
            int cc = nW + nf * 8 + ((lane & 3) << 1);
            if (cc >= Nreal) continue;
            int r0 = mW + t * 16 + (lane >> 2);
            int r1 = r0 + 8;
            float bv0 = bias ? bias[cc] : 0.0f;
            float bv1 = bias ? bias[cc + 1] : 0.0f;
            float v00 = acc[t][nf][0] + bv0;
            float v01 = acc[t][nf][1] + bv1;
            float v10 = acc[t][nf][2] + bv0;
            float v11 = acc[t][nf][3] + bv1;
            if (doRelu) {
                v00 = fmaxf(v00, 0.f); v01 = fmaxf(v01, 0.f);
                v10 = fmaxf(v10, 0.f); v11 = fmaxf(v11, 0.f);
            }
            if constexpr (OUTFMT == 2) {
                *reinterpret_cast<float2*>(oF + (size_t)r0 * Nreal + cc) = make_float2(v00, v01);
                *reinterpret_cast<float2*>(oF + (size_t)r1 * Nreal + cc) = make_float2(v10, v11);
            } else {
                __nv_bfloat16 h00 = __float2bfloat16(v00), h01 = __float2bfloat16(v01);
                __nv_bfloat16 h10 = __float2bfloat16(v10), h11 = __float2bfloat16(v11);
                __nv_bfloat16 l00 = __float2bfloat16(v00 - __bfloat162float(h00));
                __nv_bfloat16 l01 = __float2bfloat16(v01 - __bfloat162float(h01));
                __nv_bfloat16 l10 = __float2bfloat16(v10 - __bfloat162float(h10));
                __nv_bfloat16 l11 = __float2bfloat16(v11 - __bfloat162float(h11));
                *reinterpret_cast<__nv_bfloat162*>(oHi + (size_t)r0 * Nreal + cc) = __nv_bfloat162(h00, h01);
                *reinterpret_cast<__nv_bfloat162*>(oHi + (size_t)r1 * Nreal + cc) = __nv_bfloat162(h10, h11);
                *reinterpret_cast<__nv_bfloat162*>(oLo + (size_t)r0 * Nreal + cc) = __nv_bfloat162(l00, l01);
                *reinterpret_cast<__nv_bfloat162*>(oLo + (size_t)r1 * Nreal + cc) = __nv_bfloat162(l10, l11);
            }
        }
    }
}

// ============================================================================
// Fused kernel: every GEMM CTA, after its epilogue, prepacks a round-robin
// share of the NEXT layer's weight rows (fp32 -> hi/lo bf16). Same CTAs, no
// extra blocks -> no SMEM-occupancy trap (the R11 failure). The prep DRAM
// traffic overlaps the compute-bound GEMM (DRAM sits at 3-9%).
// Safe: layer i never reads prep outputs; layer i+1 is a later launch.
// ============================================================================
template<int OUTFMT>
__global__ void __launch_bounds__(GEMM_THREADS, 1)
gemm_bf16x3(const __nv_bfloat16* __restrict__ aHi, const __nv_bfloat16* __restrict__ aLo,
            const __nv_bfloat16* __restrict__ wHi, const __nv_bfloat16* __restrict__ wLo,
            const float* __restrict__ bias,
            __nv_bfloat16* __restrict__ oHi, __nv_bfloat16* __restrict__ oLo,
            float* __restrict__ oF,
            int Nreal, int Kstride, int doRelu, int mBlocks, int kLen, size_t partStride,
            const float* __restrict__ prepW,
            __nv_bfloat16* __restrict__ prepHi, __nv_bfloat16* __restrict__ prepLo,
            int prepRows, int prepK)
{
    extern __shared__ char smem[];
    const int rem = Nreal - blockIdx.x * NT;   // uniform across block
    if (rem >= 256)
        gemm_body<4, OUTFMT>(smem, aHi, aLo, wHi, wLo, bias, oHi, oLo, oF,
                             Nreal, Kstride, doRelu, mBlocks, kLen, partStride);
    else if (rem >= 128)
        gemm_body<2, OUTFMT>(smem, aHi, aLo, wHi, wLo, bias, oHi, oLo, oF,
                             Nreal, Kstride, doRelu, mBlocks, kLen, partStride);
    else
        gemm_body<1, OUTFMT>(smem, aHi, aLo, wHi, wLo, bias, oHi, oLo, oF,
                             Nreal, Kstride, doRelu, mBlocks, kLen, partStride);

    // -------- post-epilogue prepack of next layer's weights ----------------
    if (prepRows > 0) {
        int nBlocks = gridDim.x * gridDim.y;
        int lb = blockIdx.y * gridDim.x + blockIdx.x;
        for (int n = lb; n < prepRows; n += nBlocks) {
            split_row(prepW + (size_t)n * prepK,
                      prepHi + (size_t)n * prepK,
                      prepLo + (size_t)n * prepK, prepK);
        }
    }
}

// ============================================================================
// Prepack: fused concat-split (x) + w1 split-pad-K (needed before L1 itself)
// ============================================================================
#define CONCAT_BLOCKS 6144
#define W1_BLOCKS 1584
__global__ void prep_fused(const float* __restrict__ state,
                           const float* __restrict__ pref,
                           __nv_bfloat16* __restrict__ xHi, __nv_bfloat16* __restrict__ xLo,
                           const float* __restrict__ w1,
                           __nv_bfloat16* __restrict__ w1Hi, __nv_bfloat16* __restrict__ w1Lo)
{
    if (blockIdx.x < CONCAT_BLOCKS) {
        int idx = blockIdx.x * blockDim.x + threadIdx.x;   // < 8192*192
        int b = idx / 192, c = idx - b * 192;
        float v = 0.0f;
        if (c < 128)      v = state[b * 128 + c];
        else if (c < 132) v = pref[b * 4 + (c - 128)];
        __nv_bfloat16 h = __float2bfloat16(v);
        xHi[idx] = h;
        xLo[idx] = __float2bfloat16(v - __bfloat162float(h));
    } else {
        int idx = (blockIdx.x - CONCAT_BLOCKS) * blockDim.x + threadIdx.x;  // < 2112*192
        int n = idx / 192, k = idx - n * 192;
        float v = (k < 132) ? w1[n * 132 + k] : 0.0f;
        __nv_bfloat16 h = __float2bfloat16(v);
        w1Hi[idx] = h;
        w1Lo[idx] = __float2bfloat16(v - __bfloat162float(h));
    }
}

// ============================================================================
// envelope + L5 split-K combine
// ============================================================================
__global__ void envelope_combine_kernel(const float* __restrict__ qp,
                                        const float* __restrict__ bq,
                                        const float* __restrict__ pref,
                                        float* __restrict__ q,
                                        float* __restrict__ hq)
{
    int b = blockIdx.x * blockDim.x + threadIdx.x;
    if (b >= B_ROWS) return;
    const float* p0v = qp + (size_t)b * 64;
    const float* p1v = qp + (size_t)B_ROWS * 64 + (size_t)b * 64;
    float p0 = pref[b * 4 + 0], p1 = pref[b * 4 + 1];
    float p2 = pref[b * 4 + 2], p3 = pref[b * 4 + 3];
    float qv[64];
    #pragma unroll
    for (int j = 0; j < 64; j += 4) {
        float4 a = *reinterpret_cast<const float4*>(p0v + j);
        float4 c = *reinterpret_cast<const float4*>(p1v + j);
        qv[j + 0] = a.x + c.x + bq[j + 0];
        qv[j + 1] = a.y + c.y + bq[j + 1];
        qv[j + 2] = a.z + c.z + bq[j + 2];
        qv[j + 3] = a.w + c.w + bq[j + 3];
    }
    float best = -3.402823466e+38f;
    int ba = 0;
    #pragma unroll
    for (int a = 0; a < 16; a++) {
        float ip = qv[a * 4 + 0] * p0 + qv[a * 4 + 1] * p1
                 + qv[a * 4 + 2] * p2 + qv[a * 4 + 3] * p3;
        if (ip > best) { best = ip; ba = a; }
    }
    float* qrow = q + (size_t)b * 64;
    #pragma unroll
    for (int j = 0; j < 64; j += 4)
        *reinterpret_cast<float4*>(qrow + j) =
            make_float4(qv[j], qv[j + 1], qv[j + 2], qv[j + 3]);
    hq[b * 4 + 0] = qv[ba * 4 + 0];
    hq[b * 4 + 1] = qv[ba * 4 + 1];
    hq[b * 4 + 2] = qv[ba * 4 + 2];
    hq[b * 4 + 3] = qv[ba * 4 + 3];
}

// ============================================================================
// launch — #4 (ncu capture slot) = L3 fused GEMM
// ============================================================================
static inline void* sym(const void* s) { void* p; cudaGetSymbolAddress(&p, s); return p; }

extern "C" void kernel_launch(void* const* d_in, const int* in_sizes, int n_in,
                              void* d_out, int out_size)
{
    const float* state = (const float*)d_in[0];
    const float* pref  = (const float*)d_in[1];
    const float* w1 = (const float*)d_in[2];  const float* b1 = (const float*)d_in[3];
    const float* w2 = (const float*)d_in[4];  const float* b2 = (const float*)d_in[5];
    const float* w3 = (const float*)d_in[6];  const float* b3 = (const float*)d_in[7];
    const float* w4 = (const float*)d_in[8];  const float* b4 = (const float*)d_in[9];
    const float* wq = (const float*)d_in[10]; const float* bq = (const float*)d_in[11];

    float* out = (float*)d_out;
    float* hq = out;                       // [8192, 4]
    float* q  = out + (size_t)B_ROWS * 4;  // [8192, 64]

    __nv_bfloat16* xHi = (__nv_bfloat16*)sym(g_xHi);
    __nv_bfloat16* xLo = (__nv_bfloat16*)sym(g_xLo);
    __nv_bfloat16* w1Hi = (__nv_bfloat16*)sym(g_w1Hi); __nv_bfloat16* w1Lo = (__nv_bfloat16*)sym(g_w1Lo);
    __nv_bfloat16* w2Hi = (__nv_bfloat16*)sym(g_w2Hi); __nv_bfloat16* w2Lo = (__nv_bfloat16*)sym(g_w2Lo);
    __nv_bfloat16* w3Hi = (__nv_bfloat16*)sym(g_w3Hi); __nv_bfloat16* w3Lo = (__nv_bfloat16*)sym(g_w3Lo);
    __nv_bfloat16* w4Hi = (__nv_bfloat16*)sym(g_w4Hi); __nv_bfloat16* w4Lo = (__nv_bfloat16*)sym(g_w4Lo);
    __nv_bfloat16* w5Hi = (__nv_bfloat16*)sym(g_w5Hi); __nv_bfloat16* w5Lo = (__nv_bfloat16*)sym(g_w5Lo);
    __nv_bfloat16* aHi = (__nv_bfloat16*)sym(g_actAHi); __nv_bfloat16* aLo = (__nv_bfloat16*)sym(g_actALo);
    __nv_bfloat16* bHi = (__nv_bfloat16*)sym(g_actBHi); __nv_bfloat16* bLo = (__nv_bfloat16*)sym(g_actBLo);
    float* qp = (float*)sym(g_qpart);

    cudaFuncSetAttribute(gemm_bf16x3<0>, cudaFuncAttributeMaxDynamicSharedMemorySize, SMEM_TOTAL);
    cudaFuncSetAttribute(gemm_bf16x3<2>, cudaFuncAttributeMaxDynamicSharedMemorySize, SMEM_TOTAL);

    dim3 blk(GEMM_THREADS);

    // #1 concat + w1 prepack (needed by L1 itself — must precede it)
    prep_fused<<<CONCAT_BLOCKS + W1_BLOCKS, 256>>>(state, pref, xHi, xLo, w1, w1Hi, w1Lo);
    // #2 L1 (CTAs also prepack w2): [8192,192] x [2112,192] -> actA (2112)
    gemm_bf16x3<0><<<dim3(9, 64), blk, SMEM_TOTAL>>>(
        xHi, xLo, w1Hi, w1Lo, b1, aHi, aLo, nullptr, 2112, 192, 1, 64, 192, 0,
        w2, w2Hi, w2Lo, 4224, 2112);
    // #3 L2 (CTAs also prepack w3): [8192,2112] x [4224,2112] -> actB (4224)
    gemm_bf16x3<0><<<dim3(17, 64), blk, SMEM_TOTAL>>>(
        aHi, aLo, w2Hi, w2Lo, b2, bHi, bLo, nullptr, 4224, 2112, 1, 64, 2112, 0,
        w3, w3Hi, w3Lo, 8448, 4224);
    // #4 L3 (CTAs also prepack w4): [8192,4224] x [8448,4224] -> actA (8448)  <-- ncu slot
    gemm_bf16x3<0><<<dim3(33, 64), blk, SMEM_TOTAL>>>(
        bHi, bLo, w3Hi, w3Lo, b3, aHi, aLo, nullptr, 8448, 4224, 1, 64, 4224, 0,
        w4, w4Hi, w4Lo, 4224, 8448);
    // #5 L4 (CTAs also prepack w5): [8192,8448] x [4224,8448] -> actB (4224)
    gemm_bf16x3<0><<<dim3(17, 64), blk, SMEM_TOTAL>>>(
        aHi, aLo, w4Hi, w4Lo, b4, bHi, bLo, nullptr, 4224, 8448, 1, 64, 8448, 0,
        wq, w5Hi, w5Lo, 64, 4224);
    // #6 L5 split-K: [8192,4224] x [64,4224] -> 2 raw partials (no bias)
    gemm_bf16x3<2><<<dim3(1, 128), blk, SMEM_TOTAL>>>(
        bHi, bLo, w5Hi, w5Lo, nullptr, nullptr, nullptr, qp,
        64, 4224, 0, 64, 2112, (size_t)B_ROWS * 64,
        nullptr, nullptr, nullptr, 0, 0);
    // #7 combine + envelope
    envelope_combine_kernel<<<(B_ROWS + 255) / 256, 256>>>(qp, bq, pref, q, hq);
}

// round 13
// speedup vs baseline: 426.8796x; 408.8598x over previous
#include <cuda_runtime.h>
#include <cuda_bf16.h>
#include <cstdint>

// ============================================================================
// Problem constants
// ============================================================================
#define B_ROWS 8192

#define MT 128
#define NT 256
#define KC 64
#define GEMM_THREADS 256

#define STG_A_HI 0
#define STG_A_LO 16384
#define STG_W_HI 32768
#define STG_W_LO 65536
#define STAGE_BYTES 98304          // 96 KB
#define SMEM_TOTAL (2 * STAGE_BYTES)

// ---- persistent-kernel tile queue layout (m-block-major inside each layer) --
#define MBLK 64
#define NT_L1 9
#define NT_L2 17
#define NT_L3 33
#define NT_L4 17
#define Q_L1   0
#define Q_PW2  576                 // + 64*9
#define Q_L2   642                 // + 66   (w2: 4224/64 row-tiles)
#define Q_PW3  1730                // + 64*17
#define Q_L3   1862                // + 132  (w3: 8448/64)
#define Q_PW4  3974                // + 64*33
#define Q_L4   4040                // + 66   (w4: 4224/64)
#define Q_PW5  5128                // + 64*17
#define Q_L5   5130                // + 2    (w5: 64/32)
#define Q_TOTAL 5258               // + 128  (L5: 2 parts x 64 m-blocks)

// ============================================================================
// Scratch (__device__ globals; no cudaMalloc allowed)
// ============================================================================
__device__ __nv_bfloat16 g_xHi[B_ROWS * 192];
__device__ __nv_bfloat16 g_xLo[B_ROWS * 192];

__device__ __nv_bfloat16 g_w1Hi[2112 * 192],           g_w1Lo[2112 * 192];
__device__ __nv_bfloat16 g_w2Hi[(size_t)4224 * 2112],  g_w2Lo[(size_t)4224 * 2112];
__device__ __nv_bfloat16 g_w3Hi[(size_t)8448 * 4224],  g_w3Lo[(size_t)8448 * 4224];
__device__ __nv_bfloat16 g_w4Hi[(size_t)4224 * 8448],  g_w4Lo[(size_t)4224 * 8448];
__device__ __nv_bfloat16 g_w5Hi[64 * 4224],            g_w5Lo[64 * 4224];

__device__ __nv_bfloat16 g_actAHi[(size_t)B_ROWS * 8448], g_actALo[(size_t)B_ROWS * 8448];
__device__ __nv_bfloat16 g_actBHi[(size_t)B_ROWS * 4224], g_actBLo[(size_t)B_ROWS * 4224];

__device__ __align__(16) float g_qpart[2 * B_ROWS * 64];

// dependency tracking (zeroed each replay by prep_fused block 0)
__device__ int g_done[4][MBLK];    // [layer 1..4 output][m-block] n-tiles done
__device__ int g_prep[4];          // w2..w5 prep tiles done
__device__ int g_qhead;

// ============================================================================
// PTX helpers
// ============================================================================
__device__ __forceinline__ uint32_t smem_u32(const void* p) {
    uint32_t a;
    asm("{ .reg .u64 t; cvta.to.shared.u64 t, %1; cvt.u32.u64 %0, t; }"
        : "=r"(a) : "l"(p));
    return a;
}

#define CP_ASYNC16(dst, src) \
    asm volatile("cp.async.cg.shared.global [%0], [%1], 16;" :: "r"(dst), "l"(src))

#define CP_COMMIT() asm volatile("cp.async.commit_group;" ::: "memory")
#define CP_WAIT(n)  asm volatile("cp.async.wait_group %0;" :: "n"(n) : "memory")

#define LDSM4(r, addr) \
    asm volatile("ldmatrix.sync.aligned.m8n8.x4.shared.b16 {%0,%1,%2,%3}, [%4];" \
                 : "=r"((r)[0]), "=r"((r)[1]), "=r"((r)[2]), "=r"((r)[3]) : "r"(addr))

#define MMA_BF16(d, a, b0, b1) \
    asm volatile("mma.sync.aligned.m16n8k16.row.col.f32.bf16.bf16.f32 " \
                 "{%0,%1,%2,%3},{%4,%5,%6,%7},{%8,%9},{%0,%1,%2,%3};" \
                 : "+f"((d)[0]), "+f"((d)[1]), "+f"((d)[2]), "+f"((d)[3]) \
                 : "r"((a)[0]), "r"((a)[1]), "r"((a)[2]), "r"((a)[3]), \
                   "r"(b0), "r"(b1))

__device__ __forceinline__ uint32_t swz(int r, int c) {
    return (uint32_t)(r * 128 + ((c ^ (r & 7)) << 4));
}

// ---- dependency primitives (CUDA guide threadfence pattern) ----------------
__device__ __forceinline__ void wait_cnt(volatile int* c, int need) {
    if (threadIdx.x == 0) {
        while (*c < need) __nanosleep(256);
        __threadfence();
    }
    __syncthreads();
}

__device__ __forceinline__ void mark_done(int* c) {
    __threadfence();
    __syncthreads();
    if (threadIdx.x == 0) atomicAdd(c, 1);
}

// prep `rows` fp32 rows starting at row `base` into hi/lo bf16
__device__ __forceinline__ void prep_rows(const float* __restrict__ src,
                                          __nv_bfloat16* __restrict__ hi,
                                          __nv_bfloat16* __restrict__ lo,
                                          size_t base, int rows, int K)
{
    const float4* s4 = reinterpret_cast<const float4*>(src + base * K);
    uint2* dhi = reinterpret_cast<uint2*>(hi + base * K);
    uint2* dlo = reinterpret_cast<uint2*>(lo + base * K);
    int nv = rows * (K >> 2);
    for (int i = threadIdx.x; i < nv; i += GEMM_THREADS) {
        float4 v = s4[i];
        __nv_bfloat16 h0 = __float2bfloat16(v.x), h1 = __float2bfloat16(v.y);
        __nv_bfloat16 h2 = __float2bfloat16(v.z), h3 = __float2bfloat16(v.w);
        uint2 uh, ul;
        uh.x = (uint32_t)__bfloat16_as_ushort(h0) | ((uint32_t)__bfloat16_as_ushort(h1) << 16);
        uh.y = (uint32_t)__bfloat16_as_ushort(h2) | ((uint32_t)__bfloat16_as_ushort(h3) << 16);
        __nv_bfloat16 l0 = __float2bfloat16(v.x - __bfloat162float(h0));
        __nv_bfloat16 l1 = __float2bfloat16(v.y - __bfloat162float(h1));
        __nv_bfloat16 l2 = __float2bfloat16(v.z - __bfloat162float(h2));
        __nv_bfloat16 l3 = __float2bfloat16(v.w - __bfloat162float(h3));
        ul.x = (uint32_t)__bfloat16_as_ushort(l0) | ((uint32_t)__bfloat16_as_ushort(l1) << 16);
        ul.y = (uint32_t)__bfloat16_as_ushort(l2) | ((uint32_t)__bfloat16_as_ushort(l3) << 16);
        dhi[i] = uh;
        dlo[i] = ul;
    }
}

// ============================================================================
// One GEMM tile (R9-proven hot loop, explicit m0/n0/kOff — no blockIdx)
// ============================================================================
template<int NPT, int OUTFMT>
__device__ __forceinline__ void gemm_tile(
    char* smem,
    const __nv_bfloat16* __restrict__ aHi, const __nv_bfloat16* __restrict__ aLo,
    const __nv_bfloat16* __restrict__ wHi, const __nv_bfloat16* __restrict__ wLo,
    const float* __restrict__ bias,
    __nv_bfloat16* __restrict__ oHi, __nv_bfloat16* __restrict__ oLo,
    float* __restrict__ oF,
    int Nreal, int Kstride, int doRelu, int m0, int n0, int kOff, int kLen)
{
    const uint32_t sb = smem_u32(smem);
    const int tid  = threadIdx.x;
    const int wid  = tid >> 5;
    const int lane = tid & 31;
    aHi += kOff; aLo += kOff; wHi += kOff; wLo += kOff;
    const int nChunks = kLen / KC;

    auto load_chunk = [&](int c, int stage) {
        const uint32_t base = sb + stage * STAGE_BYTES;
        const int k0 = c * KC;
        #pragma unroll
        for (int i = 0; i < 4; i++) {
            int j = tid + i * GEMM_THREADS;
            int r = j >> 3, cc = j & 7;
            uint32_t d = base + swz(r, cc);
            size_t so = (size_t)(m0 + r) * Kstride + k0 + cc * 8;
            CP_ASYNC16(d + STG_A_HI, aHi + so);
            CP_ASYNC16(d + STG_A_LO, aLo + so);
        }
        #pragma unroll
        for (int i = 0; i < 2 * NPT; i++) {
            int j = tid + i * GEMM_THREADS;
            int r = j >> 3, cc = j & 7;
            uint32_t d = base + swz(r, cc);
            size_t so = (size_t)(n0 + r) * Kstride + k0 + cc * 8;
            CP_ASYNC16(d + STG_W_HI, wHi + so);
            CP_ASYNC16(d + STG_W_LO, wLo + so);
        }
    };

    float acc[4][2 * NPT][4];
    #pragma unroll
    for (int t = 0; t < 4; t++)
        #pragma unroll
        for (int nf = 0; nf < 2 * NPT; nf++)
            #pragma unroll
            for (int e = 0; e < 4; e++) acc[t][nf][e] = 0.0f;

    const int mBase = (wid & 1) * 64;
    const int nBase = (wid >> 1) * (NPT * 16);

    load_chunk(0, 0);
    CP_COMMIT();

    for (int c = 0; c < nChunks; c++) {
        if (c + 1 < nChunks) {
            load_chunk(c + 1, (c + 1) & 1);
            CP_COMMIT();
            CP_WAIT(1);
        } else {
            CP_WAIT(0);
        }
        __syncthreads();

        const uint32_t base = sb + (c & 1) * STAGE_BYTES;
        #pragma unroll
        for (int s = 0; s < 4; s++) {
            uint32_t aH[4][4], aL[4][4];
            #pragma unroll
            for (int t = 0; t < 4; t++) {
                int row = mBase + t * 16 + (lane & 15);
                int c16 = s * 2 + (lane >> 4);
                uint32_t ad = base + swz(row, c16);
                LDSM4(aH[t], ad + STG_A_HI);
                LDSM4(aL[t], ad + STG_A_LO);
            }
            #pragma unroll
            for (int p = 0; p < NPT; p++) {
                int g = lane >> 3;
                int row = nBase + p * 16 + (lane & 7) + ((g >> 1) << 3);
                int c16 = s * 2 + (g & 1);
                uint32_t wd = base + swz(row, c16);
                uint32_t bH[4], bL[4];
                LDSM4(bH, wd + STG_W_HI);
                LDSM4(bL, wd + STG_W_LO);
                #pragma unroll
                for (int t = 0; t < 4; t++) {
                    MMA_BF16(acc[t][2 * p],     aH[t], bH[0], bH[1]);
                    MMA_BF16(acc[t][2 * p + 1], aH[t], bH[2], bH[3]);
                }
                #pragma unroll
                for (int t = 0; t < 4; t++) {
                    MMA_BF16(acc[t][2 * p],     aL[t], bH[0], bH[1]);
                    MMA_BF16(acc[t][2 * p + 1], aL[t], bH[2], bH[3]);
                }
                #pragma unroll
                for (int t = 0; t < 4; t++) {
                    MMA_BF16(acc[t][2 * p],     aH[t], bL[0], bL[1]);
                    MMA_BF16(acc[t][2 * p + 1], aH[t], bL[2], bL[3]);
                }
            }
        }
        __syncthreads();
    }

    const int mW = m0 + mBase;
    const int nW = n0 + nBase;
    #pragma unroll
    for (int t = 0; t < 4; t++) {
        #pragma unroll
        for (int nf = 0; nf < 2 * NPT; nf++) {
            int cc = nW + nf * 8 + ((lane & 3) << 1);
            if (cc >= Nreal) continue;
            int r0 = mW + t * 16 + (lane >> 2);
            int r1 = r0 + 8;
            float bv0 = bias ? bias[cc] : 0.0f;
            float bv1 = bias ? bias[cc + 1] : 0.0f;
            float v00 = acc[t][nf][0] + bv0;
            float v01 = acc[t][nf][1] + bv1;
            float v10 = acc[t][nf][2] + bv0;
            float v11 = acc[t][nf][3] + bv1;
            if (doRelu) {
                v00 = fmaxf(v00, 0.f); v01 = fmaxf(v01, 0.f);
                v10 = fmaxf(v10, 0.f); v11 = fmaxf(v11, 0.f);
            }
            if constexpr (OUTFMT == 2) {
                *reinterpret_cast<float2*>(oF + (size_t)r0 * Nreal + cc) = make_float2(v00, v01);
                *reinterpret_cast<float2*>(oF + (size_t)r1 * Nreal + cc) = make_float2(v10, v11);
            } else {
                __nv_bfloat16 h00 = __float2bfloat16(v00), h01 = __float2bfloat16(v01);
                __nv_bfloat16 h10 = __float2bfloat16(v10), h11 = __float2bfloat16(v11);
                __nv_bfloat16 l00 = __float2bfloat16(v00 - __bfloat162float(h00));
                __nv_bfloat16 l01 = __float2bfloat16(v01 - __bfloat162float(h01));
                __nv_bfloat16 l10 = __float2bfloat16(v10 - __bfloat162float(h10));
                __nv_bfloat16 l11 = __float2bfloat16(v11 - __bfloat162float(h11));
                *reinterpret_cast<__nv_bfloat162*>(oHi + (size_t)r0 * Nreal + cc) = __nv_bfloat162(h00, h01);
                *reinterpret_cast<__nv_bfloat162*>(oHi + (size_t)r1 * Nreal + cc) = __nv_bfloat162(h10, h11);
                *reinterpret_cast<__nv_bfloat162*>(oLo + (size_t)r0 * Nreal + cc) = __nv_bfloat162(l00, l01);
                *reinterpret_cast<__nv_bfloat162*>(oLo + (size_t)r1 * Nreal + cc) = __nv_bfloat162(l10, l11);
            }
        }
    }
}

// ============================================================================
// Persistent mega-kernel: all 5 layers + weight prepacks, one launch.
// 148 CTAs pull tiles off a global queue; deps via counters (backward-only
// in queue order => deadlock-free). Per-tile math identical to R9.
// ============================================================================
__global__ void __launch_bounds__(GEMM_THREADS, 1)
mega_kernel(const float* __restrict__ w2, const float* __restrict__ w3,
            const float* __restrict__ w4, const float* __restrict__ wq,
            const float* __restrict__ b1, const float* __restrict__ b2,
            const float* __restrict__ b3, const float* __restrict__ b4)
{
    extern __shared__ char smem[];
    __shared__ int s_idx;

    const __nv_bfloat16 *xHi = g_xHi,  *xLo = g_xLo;
    const __nv_bfloat16 *w1H = g_w1Hi, *w1L = g_w1Lo;

    for (;;) {
        __syncthreads();                       // protect s_idx overwrite
        if (threadIdx.x == 0) s_idx = atomicAdd(&g_qhead, 1);
        __syncthreads();
        int idx = s_idx;
        if (idx >= Q_TOTAL) break;

        if (idx < Q_PW2) {                                   // ---- L1 ----
            int m = idx / NT_L1, n = idx % NT_L1;
            int n0 = n * NT;
            if (2112 - n0 >= 256)
                gemm_tile<4, 0>(smem, xHi, xLo, w1H, w1L, b1,
                                g_actAHi, g_actALo, nullptr,
                                2112, 192, 1, m * MT, n0, 0, 192);
            else                                            // tail 64 cols
                gemm_tile<1, 0>(smem, xHi, xLo, w1H, w1L, b1,
                                g_actAHi, g_actALo, nullptr,
                                2112, 192, 1, m * MT, n0, 0, 192);
            mark_done(&g_done[0][m]);
        } else if (idx < Q_L2) {                             // ---- prep w2 ----
            int j = idx - Q_PW2;
            prep_rows(w2, g_w2Hi, g_w2Lo, (size_t)j * 64, 64, 2112);
            mark_done(&g_prep[0]);
        } else if (idx < Q_PW3) {                            // ---- L2 ----
            int j = idx - Q_L2;
            int m = j / NT_L2, n = j % NT_L2;
            wait_cnt(&g_prep[0], 66);
            wait_cnt(&g_done[0][m], NT_L1);
            int n0 = n * NT;
            if (4224 - n0 >= 256)
                gemm_tile<4, 0>(smem, g_actAHi, g_actALo, g_w2Hi, g_w2Lo, b2,
                                g_actBHi, g_actBLo, nullptr,
                                4224, 2112, 1, m * MT, n0, 0, 2112);
            else                                            // tail 128 cols
                gemm_tile<2, 0>(smem, g_actAHi, g_actALo, g_w2Hi, g_w2Lo, b2,
                                g_actBHi, g_actBLo, nullptr,
                                4224, 2112, 1, m * MT, n0, 0, 2112);
            mark_done(&g_done[1][m]);
        } else if (idx < Q_L3) {                             // ---- prep w3 ----
            int j = idx - Q_PW3;
            prep_rows(w3, g_w3Hi, g_w3Lo, (size_t)j * 64, 64, 4224);
            mark_done(&g_prep[1]);
        } else if (idx < Q_PW4) {                            // ---- L3 ----
            int j = idx - Q_L3;
            int m = j / NT_L3, n = j % NT_L3;
            wait_cnt(&g_prep[1], 132);
            wait_cnt(&g_done[1][m], NT_L2);
            gemm_tile<4, 0>(smem, g_actBHi, g_actBLo, g_w3Hi, g_w3Lo, b3,
                            g_actAHi, g_actALo, nullptr,
                            8448, 4224, 1, m * MT, n * NT, 0, 4224);
            mark_done(&g_done[2][m]);
        } else if (idx < Q_L4) {                             // ---- prep w4 ----
            int j = idx - Q_PW4;
            prep_rows(w4, g_w4Hi, g_w4Lo, (size_t)j * 64, 64, 8448);
            mark_done(&g_prep[2]);
        } else if (idx < Q_PW5) {                            // ---- L4 ----
            int j = idx - Q_L4;
            int m = j / NT_L4, n = j % NT_L4;
            wait_cnt(&g_prep[2], 66);
            wait_cnt(&g_done[2][m], NT_L3);
            int n0 = n * NT;
            if (4224 - n0 >= 256)
                gemm_tile<4, 0>(smem, g_actAHi, g_actALo, g_w4Hi, g_w4Lo, b4,
                                g_actBHi, g_actBLo, nullptr,
                                4224, 8448, 1, m * MT, n0, 0, 8448);
            else
                gemm_tile<2, 0>(smem, g_actAHi, g_actALo, g_w4Hi, g_w4Lo, b4,
                                g_actBHi, g_actBLo, nullptr,
                                4224, 8448, 1, m * MT, n0, 0, 8448);
            mark_done(&g_done[3][m]);
        } else if (idx < Q_L5) {                             // ---- prep w5 ----
            int j = idx - Q_PW5;
            prep_rows(wq, g_w5Hi, g_w5Lo, (size_t)j * 32, 32, 4224);
            mark_done(&g_prep[3]);
        } else {                                             // ---- L5 split-K ----
            int j = idx - Q_L5;
            int part = j >> 6, m = j & 63;
            wait_cnt(&g_prep[3], 2);
            wait_cnt(&g_done[3][m], NT_L4);
            gemm_tile<1, 2>(smem, g_actBHi, g_actBLo, g_w5Hi, g_w5Lo, nullptr,
                            nullptr, nullptr, g_qpart + (size_t)part * B_ROWS * 64,
                            64, 4224, 0, m * MT, 0, part * 2112, 2112);
            // no consumer inside this kernel (envelope is next launch)
        }
    }
}

// ============================================================================
// Prepack: counters zero + concat-split (x) + w1 split-pad-K
// ============================================================================
#define CONCAT_BLOCKS 6144
#define W1_BLOCKS 1584
__global__ void prep_fused(const float* __restrict__ state,
                           const float* __restrict__ pref,
                           const float* __restrict__ w1)
{
    int t = threadIdx.x;
    if (blockIdx.x == 0) {                 // zero dependency counters
        if (t < 256)       ((int*)g_done)[t] = 0;
        else if (t < 260)  g_prep[t - 256] = 0;
        else if (t == 260) g_qhead = 0;
    }
    if (blockIdx.x < CONCAT_BLOCKS) {
        int idx = blockIdx.x * blockDim.x + t;             // < 8192*192
        int b = idx / 192, c = idx - b * 192;
        float v = 0.0f;
        if (c < 128)      v = state[b * 128 + c];
        else if (c < 132) v = pref[b * 4 + (c - 128)];
        __nv_bfloat16 h = __float2bfloat16(v);
        g_xHi[idx] = h;
        g_xLo[idx] = __float2bfloat16(v - __bfloat162float(h));
    } else {
        int idx = (blockIdx.x - CONCAT_BLOCKS) * blockDim.x + t;  // < 2112*192
        int n = idx / 192, k = idx - n * 192;
        float v = (k < 132) ? w1[n * 132 + k] : 0.0f;
        __nv_bfloat16 h = __float2bfloat16(v);
        g_w1Hi[idx] = h;
        g_w1Lo[idx] = __float2bfloat16(v - __bfloat162float(h));
    }
}

// ============================================================================
// envelope + L5 split-K combine
// ============================================================================
__global__ void envelope_combine_kernel(const float* __restrict__ bq,
                                        const float* __restrict__ pref,
                                        float* __restrict__ q,
                                        float* __restrict__ hq)
{
    int b = blockIdx.x * blockDim.x + threadIdx.x;
    if (b >= B_ROWS) return;
    const float* p0v = g_qpart + (size_t)b * 64;
    const float* p1v = g_qpart + (size_t)B_ROWS * 64 + (size_t)b * 64;
    float p0 = pref[b * 4 + 0], p1 = pref[b * 4 + 1];
    float p2 = pref[b * 4 + 2], p3 = pref[b * 4 + 3];
    float qv[64];
    #pragma unroll
    for (int j = 0; j < 64; j += 4) {
        float4 a = *reinterpret_cast<const float4*>(p0v + j);
        float4 c = *reinterpret_cast<const float4*>(p1v + j);
        qv[j + 0] = a.x + c.x + bq[j + 0];
        qv[j + 1] = a.y + c.y + bq[j + 1];
        qv[j + 2] = a.z + c.z + bq[j + 2];
        qv[j + 3] = a.w + c.w + bq[j + 3];
    }
    float best = -3.402823466e+38f;
    int ba = 0;
    #pragma unroll
    for (int a = 0; a < 16; a++) {
        float ip = qv[a * 4 + 0] * p0 + qv[a * 4 + 1] * p1
                 + qv[a * 4 + 2] * p2 + qv[a * 4 + 3] * p3;
        if (ip > best) { best = ip; ba = a; }
    }
    float* qrow = q + (size_t)b * 64;
    #pragma unroll
    for (int j = 0; j < 64; j += 4)
        *reinterpret_cast<float4*>(qrow + j) =
            make_float4(qv[j], qv[j + 1], qv[j + 2], qv[j + 3]);
    hq[b * 4 + 0] = qv[ba * 4 + 0];
    hq[b * 4 + 1] = qv[ba * 4 + 1];
    hq[b * 4 + 2] = qv[ba * 4 + 2];
    hq[b * 4 + 3] = qv[ba * 4 + 3];
}

// ============================================================================
// launch
// ============================================================================
extern "C" void kernel_launch(void* const* d_in, const int* in_sizes, int n_in,
                              void* d_out, int out_size)
{
    const float* state = (const float*)d_in[0];
    const float* pref  = (const float*)d_in[1];
    const float* w1 = (const float*)d_in[2];  const float* b1 = (const float*)d_in[3];
    const float* w2 = (const float*)d_in[4];  const float* b2 = (const float*)d_in[5];
    const float* w3 = (const float*)d_in[6];  const float* b3 = (const float*)d_in[7];
    const float* w4 = (const float*)d_in[8];  const float* b4 = (const float*)d_in[9];
    const float* wq = (const float*)d_in[10]; const float* bq = (const float*)d_in[11];

    float* out = (float*)d_out;
    float* hq = out;                       // [8192, 4]
    float* q  = out + (size_t)B_ROWS * 4;  // [8192, 64]

    cudaFuncSetAttribute(mega_kernel,
                         cudaFuncAttributeMaxDynamicSharedMemorySize, SMEM_TOTAL);

    // #1 counters zero + concat + w1 prepack
    prep_fused<<<CONCAT_BLOCKS + W1_BLOCKS, 256>>>(state, pref, w1);
    // #2 persistent mega-kernel: L1..L5 + w2..w5 prepacks
    mega_kernel<<<148, GEMM_THREADS, SMEM_TOTAL>>>(w2, w3, w4, wq, b1, b2, b3, b4);
    // #3 combine + envelope
    envelope_combine_kernel<<<(B_ROWS + 255) / 256, 256>>>(bq, pref, q, hq);
}